// round 14
// baseline (speedup 1.0000x reference)
#include <cuda_runtime.h>
#include <cuda_fp16.h>
#include <math.h>
#include <stdint.h>

// Problem constants: B=2,S=2048 -> N=4096 tokens
#define NTOK 4096
#define DDIM 1024
#define NEXP 8
#define HDIM 4096
#define MTOT (NTOK * 2)
#define MPAD 192
#define MAXTILE 72

// ---------------- device scratch (static; zero-initialized) -----------------
__device__ __half g_hbuf[(size_t)(MTOT + MPAD) * HDIM];
__device__ __half g_xbuf[(size_t)(MTOT + MPAD) * DDIM];
__device__ __half g_w1h[(size_t)NEXP * DDIM * HDIM];
__device__ __half g_w2h[(size_t)NEXP * HDIM * DDIM];
__device__ int    g_perm[MTOT + MPAD];
__device__ float  g_wgt[MTOT + MPAD];
__device__ int    g_counts[NEXP];
__device__ int    g_offsets[NEXP + 1];
__device__ int    g_cursor[NEXP];
__device__ float  g_enorm[NEXP];
__device__ int    g_tok_e[NTOK * 2];
__device__ float  g_tok_w[NTOK * 2];
__device__ int2   g_tile[MAXTILE];
__device__ int    g_route_done;

// ================= helpers ===================================================
__device__ __forceinline__ uint32_t smem_u32(const void* p) {
    uint32_t a;
    asm("{ .reg .u64 t; cvta.to.shared.u64 t, %1; cvt.u32.u64 %0, t; }" : "=r"(a) : "l"(p));
    return a;
}
__device__ __forceinline__ void cp16(uint32_t dst, const void* src) {
    asm volatile("cp.async.cg.shared.global [%0], [%1], 16;" :: "r"(dst), "l"(src) : "memory");
}
__device__ __forceinline__ void cp_commit() {
    asm volatile("cp.async.commit_group;" ::: "memory");
}
__device__ __forceinline__ uint32_t pack2(float a, float b) {
    __half2 h = __floats2half2_rn(a, b);
    return *reinterpret_cast<uint32_t*>(&h);
}
__device__ __forceinline__ void ldm_x4(uint32_t r[4], uint32_t addr) {
    asm volatile("ldmatrix.sync.aligned.m8n8.x4.shared.b16 {%0,%1,%2,%3}, [%4];"
        : "=r"(r[0]), "=r"(r[1]), "=r"(r[2]), "=r"(r[3]) : "r"(addr));
}
__device__ __forceinline__ void ldm_x4t(uint32_t r[4], uint32_t addr) {
    asm volatile("ldmatrix.sync.aligned.m8n8.x4.trans.shared.b16 {%0,%1,%2,%3}, [%4];"
        : "=r"(r[0]), "=r"(r[1]), "=r"(r[2]), "=r"(r[3]) : "r"(addr));
}
__device__ __forceinline__ void mma_f16(float c[4], const uint32_t a[4],
                                        uint32_t b0, uint32_t b1) {
    asm volatile(
        "mma.sync.aligned.m16n8k16.row.col.f32.f16.f16.f32 "
        "{%0,%1,%2,%3}, {%4,%5,%6,%7}, {%8,%9}, {%0,%1,%2,%3};"
        : "+f"(c[0]), "+f"(c[1]), "+f"(c[2]), "+f"(c[3])
        : "r"(a[0]), "r"(a[1]), "r"(a[2]), "r"(a[3]), "r"(b0), "r"(b1));
}
__device__ __forceinline__ void conv8(const float4* __restrict__ src,
                                      uint4* __restrict__ dst, int j) {
    float4 v0 = src[2 * j], v1 = src[2 * j + 1];
    uint4 o;
    o.x = pack2(v0.x, v0.y); o.y = pack2(v0.z, v0.w);
    o.z = pack2(v1.x, v1.y); o.w = pack2(v1.z, v1.w);
    dst[j] = o;
}
#define WN8 (NEXP * DDIM * HDIM / 8)

// ================= prep: zero out | expert norms ==============================
#define NZB 4096
__global__ void k_prep(float* __restrict__ out, const float* __restrict__ emb)
{
    const int b = blockIdx.x;
    if (b < NZB) {
        int i = b * 256 + threadIdx.x;
        ((float4*)out)[i] = make_float4(0.f, 0.f, 0.f, 0.f);
        if (b == 0 && threadIdx.x < NEXP) {
            g_counts[threadIdx.x] = 0;
            g_cursor[threadIdx.x] = 0;
            if (threadIdx.x == 0) g_route_done = 0;
        }
    } else {
        __shared__ float red[256];
        int e = b - NZB;
        float s = 0.f;
        for (int k = threadIdx.x; k < DDIM; k += 256) {
            float v = emb[e * DDIM + k];
            s += v * v;
        }
        red[threadIdx.x] = s;
        __syncthreads();
        for (int off = 128; off > 0; off >>= 1) {
            if (threadIdx.x < off) red[threadIdx.x] += red[threadIdx.x + off];
            __syncthreads();
        }
        if (threadIdx.x == 0) g_enorm[e] = sqrtf(red[0]);
    }
}

// ============ fused route + W1->fp16 + inline scheduler (last block) =========
#define NRB 512           // routing blocks (8 warps => 8 tokens each)
#define NCV1 1024         // W1 conversion blocks
__global__ void k_route(const float* __restrict__ x,
                        const float* __restrict__ emb,
                        const float* __restrict__ cache,
                        const float4* __restrict__ w1, uint4* __restrict__ w1h)
{
    if (blockIdx.x >= NRB) {
        int i = (blockIdx.x - NRB) * 256 + threadIdx.x;
        const int stride = NCV1 * 256;
        for (; i < WN8; i += stride) conv8(w1, w1h, i);
        return;
    }

    int tok  = blockIdx.x * 8 + (threadIdx.x >> 5);
    int lane = threadIdx.x & 31;

    const float* t = x + (size_t)tok * DDIM;
    float dot[NEXP];
#pragma unroll
    for (int e = 0; e < NEXP; e++) dot[e] = 0.f;
    float tsq = 0.f;
    for (int k = lane; k < DDIM; k += 32) {
        float tv = t[k];
        tsq += tv * tv;
#pragma unroll
        for (int e = 0; e < NEXP; e++) dot[e] += tv * emb[e * DDIM + k];
    }
#pragma unroll
    for (int off = 16; off > 0; off >>= 1) {
        tsq += __shfl_xor_sync(0xffffffffu, tsq, off);
#pragma unroll
        for (int e = 0; e < NEXP; e++)
            dot[e] += __shfl_xor_sync(0xffffffffu, dot[e], off);
    }
    if (lane == 0) {
        float tn = sqrtf(tsq) + 1e-8f;
        int excl = 0;
        float mn = dot[0];
#pragma unroll
        for (int e = 1; e < NEXP; e++)
            if (dot[e] <= mn) { mn = dot[e]; excl = e; }
        float score[NEXP];
#pragma unroll
        for (int e = 0; e < NEXP; e++)
            score[e] = dot[e] / (tn * (g_enorm[e] + 1e-8f)) + 0.1f * cache[e];
        int i1 = -1, i2 = -1;
        float s1 = -1e30f, s2 = -1e30f;
#pragma unroll
        for (int e = 0; e < NEXP; e++) {
            if (e == excl) continue;
            float sc = score[e];
            if (sc > s1)      { s2 = s1; i2 = i1; s1 = sc; i1 = e; }
            else if (sc > s2) { s2 = sc; i2 = e; }
        }
        float w1v = 1.f / (1.f + expf(s2 - s1));
        float w2v = 1.f - w1v;
        g_tok_e[2 * tok + 0] = i1;
        g_tok_e[2 * tok + 1] = i2;
        g_tok_w[2 * tok + 0] = w1v;
        g_tok_w[2 * tok + 1] = w2v;
        atomicAdd(&g_counts[i1], 1);
        atomicAdd(&g_counts[i2], 1);
    }

    // ---- last-routing-block-done: build offsets + tile table inline ----
    __syncthreads();
    __threadfence();
    if (threadIdx.x == 0) {
        int done = atomicAdd(&g_route_done, 1);
        if (done == NRB - 1) {
            __threadfence();   // acquire: all blocks' count atomics visible
            int cnt[NEXP];
#pragma unroll
            for (int e = 0; e < NEXP; e++) cnt[e] = atomicAdd(&g_counts[e], 0);
            int acc = 0;
#pragma unroll
            for (int e = 0; e < NEXP; e++) { g_offsets[e] = acc; acc += cnt[e]; }
            g_offsets[NEXP] = acc;
            int nt = 0;
#pragma unroll
            for (int e = 0; e < NEXP; e++)
                for (int m0 = 0; m0 < cnt[e]; m0 += 128)
                    g_tile[nt++] = make_int2(e, m0);
            while (nt < MAXTILE) g_tile[nt++] = make_int2(-1, 0);
            __threadfence();
        }
    }
}

// fused scatter + gather: block = (token, slot) assignment; copies row to xbuf
__global__ void k_scatgather(const float* __restrict__ x)
{
    __shared__ int s_pos;
    const int idx = blockIdx.x;          // 0..MTOT-1
    const int tok = idx >> 1;
    if (threadIdx.x == 0) {
        int e = g_tok_e[idx];
        int pos = g_offsets[e] + atomicAdd(&g_cursor[e], 1);
        g_perm[pos] = tok;
        g_wgt[pos]  = g_tok_w[idx];
        s_pos = pos;
    }
    __syncthreads();
    const int pos = s_pos;
    const float4* s = (const float4*)(x + (size_t)tok * DDIM);
    uint4* d = (uint4*)(g_xbuf + (size_t)pos * DDIM);
    int i = threadIdx.x;                 // 128 threads x 8 floats
    float4 v0 = s[2 * i], v1 = s[2 * i + 1];
    uint4 o;
    o.x = pack2(v0.x, v0.y); o.y = pack2(v0.z, v0.w);
    o.z = pack2(v1.x, v1.y); o.w = pack2(v1.z, v1.w);
    d[i] = o;
}

// ================= fp16 tensor-core grouped GEMM =============================
// CTA tile 128(M) x 256(N), K-chunk 64, 3-stage cp.async pipeline (half the
// barrier count of the K-chunk-32/4-stage version; identical traffic/tiles).
// 8 warps 2x4; warp tile 64x64. SMEM halves: A [128][72], B k-major [64][264].
// GEMM1 additionally carries CONV_ROWS early grid.y rows that convert W2->fp16.
#define ASTR 72
#define BSTR 264
#define A_HALVES (128 * ASTR)              // 9216
#define B_HALVES (64 * BSTR)               // 16896
#define STAGE_BYTES ((A_HALVES + B_HALVES) * 2)   // 52224
#define NSTAGE 3
#define SMEM_BYTES (NSTAGE * STAGE_BYTES)  // 156672
#define CONV_ROWS 4        // 4 x 16 = 64 conversion CTAs (GEMM1 only)

template<int KTOT, int NDIM, bool IS_G1>
__global__ __launch_bounds__(256)
void k_tc(const __half* __restrict__ Asrc, const __half* __restrict__ Bsrc,
          const float* __restrict__ bias, float* __restrict__ outp,
          const float4* __restrict__ cvsrc, uint4* __restrict__ cvdst)
{
    if (IS_G1 && blockIdx.y < CONV_ROWS) {
        // W2 fp32->fp16 conversion, scheduled in the first wave of GEMM1
        const int cid = blockIdx.y * gridDim.x + blockIdx.x;   // 0..63
        int i = cid * 256 + threadIdx.x;
        const int stride = CONV_ROWS * 16 * 256;
        for (; i < WN8; i += stride) conv8(cvsrc, cvdst, i);
        return;
    }
    const int2 tl = g_tile[blockIdx.y - (IS_G1 ? CONV_ROWS : 0)];
    if (tl.x < 0) return;
    const int e  = tl.x;
    const int m0 = tl.y;
    const int n0 = blockIdx.x * 256;
    const int base = g_offsets[e];
    const int cnt  = g_offsets[e + 1] - base;

    extern __shared__ __half smh[];
    const uint32_t s0 = smem_u32(smh);

    const int tid  = threadIdx.x;
    const int wid  = tid >> 5, lane = tid & 31;
    const int wm   = wid >> 2, wn = wid & 3;
    const int lr   = lane >> 2, lc = lane & 3;

    const __half* Abase = Asrc + (size_t)(base + m0) * KTOT;
    const __half* Bbase = Bsrc + (size_t)e * KTOT * NDIM + n0;

    float acc[4][8][4];
#pragma unroll
    for (int i = 0; i < 4; i++)
#pragma unroll
        for (int j = 0; j < 8; j++)
#pragma unroll
            for (int k = 0; k < 4; k++) acc[i][j][k] = 0.f;

    constexpr int NC = KTOT / 64;

    // per-thread cp.async assignments (256 threads, K-chunk 64)
    // A: 128 rows x 64 halves = 1024 x 16B; thread -> row tid>>1, 4 chunks
    const int am  = tid >> 1;
    const int aj  = (tid & 1) * 4;
    // B: 64 rows x 256 halves = 2048 x 16B; thread -> row tid>>2, 8 chunks
    const int bk  = tid >> 2;
    const int bj  = (tid & 3) * 8;

    auto load_chunk = [&](int c) {
        const uint32_t sa = s0 + (uint32_t)(c % NSTAGE) * STAGE_BYTES;
        const uint32_t sb = sa + A_HALVES * 2;
        const int k0 = c * 64;
#pragma unroll
        for (int j = 0; j < 4; j++)
            cp16(sa + (uint32_t)(am * ASTR + (aj + j) * 8) * 2,
                 Abase + (size_t)am * KTOT + k0 + (aj + j) * 8);
#pragma unroll
        for (int j = 0; j < 8; j++)
            cp16(sb + (uint32_t)(bk * BSTR + (bj + j) * 8) * 2,
                 Bbase + (size_t)(k0 + bk) * NDIM + (bj + j) * 8);
        cp_commit();
    };

    load_chunk(0);
    load_chunk(1);

    const uint32_t a_off = (uint32_t)((wm * 64 + (lane & 15)) * ASTR + (lane >> 4) * 8) * 2;
    const uint32_t b_off = (uint32_t)(((lane & 7) + 8 * ((lane >> 3) & 1)) * BSTR
                                      + wn * 64 + 8 * (lane >> 4)) * 2 + A_HALVES * 2;

#pragma unroll 1
    for (int c = 0; c < NC; c++) {
        asm volatile("cp.async.wait_group 1;" ::: "memory");
        __syncthreads();
        if (c + 2 < NC) load_chunk(c + 2);
        else cp_commit();

        const uint32_t st = s0 + (uint32_t)(c % NSTAGE) * STAGE_BYTES;
#pragma unroll
        for (int kk = 0; kk < 4; kk++) {
            uint32_t a[4][4], b[4][4];
#pragma unroll
            for (int mt = 0; mt < 4; mt++)
                ldm_x4(a[mt], st + a_off + (uint32_t)(mt * 16 * ASTR + kk * 16) * 2);
#pragma unroll
            for (int np = 0; np < 4; np++)
                ldm_x4t(b[np], st + b_off + (uint32_t)(np * 16 + kk * 16 * BSTR) * 2);
#pragma unroll
            for (int mt = 0; mt < 4; mt++)
#pragma unroll
                for (int nt = 0; nt < 8; nt++)
                    mma_f16(acc[mt][nt], a[mt], b[nt >> 1][(nt & 1) * 2],
                            b[nt >> 1][(nt & 1) * 2 + 1]);
        }
    }

    // ---- epilogue
#pragma unroll
    for (int mt = 0; mt < 4; mt++) {
        const int r0 = m0 + wm * 64 + mt * 16 + lr;
        const int r1 = r0 + 8;
        const bool v0 = r0 < cnt, v1 = r1 < cnt;
        int tok0 = 0, tok1 = 0;
        float wt0 = 0.f, wt1 = 0.f;
        if (!IS_G1) {
            tok0 = g_perm[base + r0]; wt0 = g_wgt[base + r0];
            tok1 = g_perm[base + r1]; wt1 = g_wgt[base + r1];
        }
#pragma unroll
        for (int nt = 0; nt < 8; nt++) {
            const int col = n0 + wn * 64 + nt * 8 + 2 * lc;
            const float bv0 = __ldg(bias + e * NDIM + col);
            const float bv1 = __ldg(bias + e * NDIM + col + 1);
            float c0 = acc[mt][nt][0] + bv0;
            float c1 = acc[mt][nt][1] + bv1;
            float c2 = acc[mt][nt][2] + bv0;
            float c3 = acc[mt][nt][3] + bv1;
            if (IS_G1) {
                c0 = 0.5f * c0 * (1.f + erff(c0 * 0.70710678118654752f));
                c1 = 0.5f * c1 * (1.f + erff(c1 * 0.70710678118654752f));
                c2 = 0.5f * c2 * (1.f + erff(c2 * 0.70710678118654752f));
                c3 = 0.5f * c3 * (1.f + erff(c3 * 0.70710678118654752f));
                __half* hp = (__half*)outp;
                if (v0) *(uint32_t*)&hp[(size_t)(base + r0) * NDIM + col] = pack2(c0, c1);
                if (v1) *(uint32_t*)&hp[(size_t)(base + r1) * NDIM + col] = pack2(c2, c3);
            } else {
                if (v0) {
                    atomicAdd(&outp[(size_t)tok0 * NDIM + col],     wt0 * c0);
                    atomicAdd(&outp[(size_t)tok0 * NDIM + col + 1], wt0 * c1);
                }
                if (v1) {
                    atomicAdd(&outp[(size_t)tok1 * NDIM + col],     wt1 * c2);
                    atomicAdd(&outp[(size_t)tok1 * NDIM + col + 1], wt1 * c3);
                }
            }
        }
    }
}

// ================= host side =================================================
extern "C" void kernel_launch(void* const* d_in, const int* in_sizes, int n_in,
                              void* d_out, int out_size)
{
    const float* x     = (const float*)d_in[0];
    const float* emb   = (const float*)d_in[1];
    const float* W1    = (const float*)d_in[2];
    const float* b1    = (const float*)d_in[3];
    const float* W2    = (const float*)d_in[4];
    const float* b2    = (const float*)d_in[5];
    const float* cache = (const float*)d_in[6];
    float* out = (float*)d_out;

    void *xbuf, *hbuf, *w1h, *w2h;
    cudaGetSymbolAddress(&xbuf, g_xbuf);
    cudaGetSymbolAddress(&hbuf, g_hbuf);
    cudaGetSymbolAddress(&w1h, g_w1h);
    cudaGetSymbolAddress(&w2h, g_w2h);

    cudaFuncSetAttribute(k_tc<DDIM, HDIM, true>,
                         cudaFuncAttributeMaxDynamicSharedMemorySize, SMEM_BYTES);
    cudaFuncSetAttribute(k_tc<HDIM, DDIM, false>,
                         cudaFuncAttributeMaxDynamicSharedMemorySize, SMEM_BYTES);

    // zero + expert norms (tiny)
    k_prep<<<NZB + NEXP, 256>>>(out, emb);
    // routing + W1 conversion + inline scheduler (last routing block)
    k_route<<<NRB + NCV1, 256>>>(x, emb, cache, (const float4*)W1, (uint4*)w1h);
    // fused scatter + gather-convert
    k_scatgather<<<MTOT, 128>>>(x);

    // GEMM1: h = gelu(xbuf @ W1 + b1); first 64 CTAs convert W2 (for GEMM2)
    {
        dim3 grid(HDIM / 256, MAXTILE + CONV_ROWS);
        k_tc<DDIM, HDIM, true><<<grid, 256, SMEM_BYTES>>>(
            (const __half*)xbuf, (const __half*)w1h, b1, (float*)hbuf,
            (const float4*)W2, (uint4*)w2h);
    }
    // GEMM2: out[tok] += w * (hbuf @ W2 + b2)
    {
        dim3 grid(DDIM / 256, MAXTILE);
        k_tc<HDIM, DDIM, false><<<grid, 256, SMEM_BYTES>>>(
            (const __half*)hbuf, (const __half*)w2h, b2, out,
            nullptr, nullptr);
    }
}

// round 15
// speedup vs baseline: 1.0854x; 1.0854x over previous
#include <cuda_runtime.h>
#include <cuda_fp16.h>
#include <math.h>
#include <stdint.h>

// Problem constants: B=2,S=2048 -> N=4096 tokens
#define NTOK 4096
#define DDIM 1024
#define NEXP 8
#define HDIM 4096
#define MTOT (NTOK * 2)
#define MPAD 192
#define MAXTILE 72

// ---------------- device scratch (static; zero-initialized) -----------------
__device__ __half g_hbuf[(size_t)(MTOT + MPAD) * HDIM];
__device__ __half g_xbuf[(size_t)(MTOT + MPAD) * DDIM];
__device__ __half g_w1h[(size_t)NEXP * DDIM * HDIM];
__device__ __half g_w2h[(size_t)NEXP * HDIM * DDIM];
__device__ int    g_perm[MTOT + MPAD];
__device__ float  g_wgt[MTOT + MPAD];
__device__ int    g_counts[NEXP];
__device__ int    g_offsets[NEXP + 1];
__device__ int    g_cursor[NEXP];
__device__ float  g_enorm[NEXP];
__device__ int    g_tok_e[NTOK * 2];
__device__ float  g_tok_w[NTOK * 2];
__device__ int2   g_tile[MAXTILE];
__device__ int    g_route_done;

// ================= helpers ===================================================
__device__ __forceinline__ uint32_t smem_u32(const void* p) {
    uint32_t a;
    asm("{ .reg .u64 t; cvta.to.shared.u64 t, %1; cvt.u32.u64 %0, t; }" : "=r"(a) : "l"(p));
    return a;
}
__device__ __forceinline__ void cp16(uint32_t dst, const void* src) {
    asm volatile("cp.async.cg.shared.global [%0], [%1], 16;" :: "r"(dst), "l"(src) : "memory");
}
__device__ __forceinline__ void cp_commit() {
    asm volatile("cp.async.commit_group;" ::: "memory");
}
__device__ __forceinline__ uint32_t pack2(float a, float b) {
    __half2 h = __floats2half2_rn(a, b);
    return *reinterpret_cast<uint32_t*>(&h);
}
__device__ __forceinline__ void ldm_x4(uint32_t r[4], uint32_t addr) {
    asm volatile("ldmatrix.sync.aligned.m8n8.x4.shared.b16 {%0,%1,%2,%3}, [%4];"
        : "=r"(r[0]), "=r"(r[1]), "=r"(r[2]), "=r"(r[3]) : "r"(addr));
}
__device__ __forceinline__ void ldm_x4t(uint32_t r[4], uint32_t addr) {
    asm volatile("ldmatrix.sync.aligned.m8n8.x4.trans.shared.b16 {%0,%1,%2,%3}, [%4];"
        : "=r"(r[0]), "=r"(r[1]), "=r"(r[2]), "=r"(r[3]) : "r"(addr));
}
__device__ __forceinline__ void mma_f16(float c[4], const uint32_t a[4],
                                        uint32_t b0, uint32_t b1) {
    asm volatile(
        "mma.sync.aligned.m16n8k16.row.col.f32.f16.f16.f32 "
        "{%0,%1,%2,%3}, {%4,%5,%6,%7}, {%8,%9}, {%0,%1,%2,%3};"
        : "+f"(c[0]), "+f"(c[1]), "+f"(c[2]), "+f"(c[3])
        : "r"(a[0]), "r"(a[1]), "r"(a[2]), "r"(a[3]), "r"(b0), "r"(b1));
}
__device__ __forceinline__ void conv8(const float4* __restrict__ src,
                                      uint4* __restrict__ dst, int j) {
    float4 v0 = src[2 * j], v1 = src[2 * j + 1];
    uint4 o;
    o.x = pack2(v0.x, v0.y); o.y = pack2(v0.z, v0.w);
    o.z = pack2(v1.x, v1.y); o.w = pack2(v1.z, v1.w);
    dst[j] = o;
}
#define WN8 (NEXP * DDIM * HDIM / 8)

// ================= prep: zero out | expert norms ==============================
#define NZB 4096
__global__ void k_prep(float* __restrict__ out, const float* __restrict__ emb)
{
    const int b = blockIdx.x;
    if (b < NZB) {
        int i = b * 256 + threadIdx.x;
        ((float4*)out)[i] = make_float4(0.f, 0.f, 0.f, 0.f);
        if (b == 0 && threadIdx.x < NEXP) {
            g_counts[threadIdx.x] = 0;
            g_cursor[threadIdx.x] = 0;
            if (threadIdx.x == 0) g_route_done = 0;
        }
    } else {
        __shared__ float red[256];
        int e = b - NZB;
        float s = 0.f;
        for (int k = threadIdx.x; k < DDIM; k += 256) {
            float v = emb[e * DDIM + k];
            s += v * v;
        }
        red[threadIdx.x] = s;
        __syncthreads();
        for (int off = 128; off > 0; off >>= 1) {
            if (threadIdx.x < off) red[threadIdx.x] += red[threadIdx.x + off];
            __syncthreads();
        }
        if (threadIdx.x == 0) g_enorm[e] = sqrtf(red[0]);
    }
}

// ============ fused route + W1->fp16 + inline scheduler (last block) =========
#define NRB 512           // routing blocks (8 warps => 8 tokens each)
#define NCV1 1024         // W1 conversion blocks
__global__ void k_route(const float* __restrict__ x,
                        const float* __restrict__ emb,
                        const float* __restrict__ cache,
                        const float4* __restrict__ w1, uint4* __restrict__ w1h)
{
    if (blockIdx.x >= NRB) {
        int i = (blockIdx.x - NRB) * 256 + threadIdx.x;
        const int stride = NCV1 * 256;
        for (; i < WN8; i += stride) conv8(w1, w1h, i);
        return;
    }

    int tok  = blockIdx.x * 8 + (threadIdx.x >> 5);
    int lane = threadIdx.x & 31;

    const float* t = x + (size_t)tok * DDIM;
    float dot[NEXP];
#pragma unroll
    for (int e = 0; e < NEXP; e++) dot[e] = 0.f;
    float tsq = 0.f;
    for (int k = lane; k < DDIM; k += 32) {
        float tv = t[k];
        tsq += tv * tv;
#pragma unroll
        for (int e = 0; e < NEXP; e++) dot[e] += tv * emb[e * DDIM + k];
    }
#pragma unroll
    for (int off = 16; off > 0; off >>= 1) {
        tsq += __shfl_xor_sync(0xffffffffu, tsq, off);
#pragma unroll
        for (int e = 0; e < NEXP; e++)
            dot[e] += __shfl_xor_sync(0xffffffffu, dot[e], off);
    }
    if (lane == 0) {
        float tn = sqrtf(tsq) + 1e-8f;
        int excl = 0;
        float mn = dot[0];
#pragma unroll
        for (int e = 1; e < NEXP; e++)
            if (dot[e] <= mn) { mn = dot[e]; excl = e; }
        float score[NEXP];
#pragma unroll
        for (int e = 0; e < NEXP; e++)
            score[e] = dot[e] / (tn * (g_enorm[e] + 1e-8f)) + 0.1f * cache[e];
        int i1 = -1, i2 = -1;
        float s1 = -1e30f, s2 = -1e30f;
#pragma unroll
        for (int e = 0; e < NEXP; e++) {
            if (e == excl) continue;
            float sc = score[e];
            if (sc > s1)      { s2 = s1; i2 = i1; s1 = sc; i1 = e; }
            else if (sc > s2) { s2 = sc; i2 = e; }
        }
        float w1v = 1.f / (1.f + expf(s2 - s1));
        float w2v = 1.f - w1v;
        g_tok_e[2 * tok + 0] = i1;
        g_tok_e[2 * tok + 1] = i2;
        g_tok_w[2 * tok + 0] = w1v;
        g_tok_w[2 * tok + 1] = w2v;
        atomicAdd(&g_counts[i1], 1);
        atomicAdd(&g_counts[i2], 1);
    }

    // ---- last-routing-block-done: build offsets + tile table inline ----
    __syncthreads();
    __threadfence();
    if (threadIdx.x == 0) {
        int done = atomicAdd(&g_route_done, 1);
        if (done == NRB - 1) {
            __threadfence();   // acquire: all blocks' count atomics visible
            int cnt[NEXP];
#pragma unroll
            for (int e = 0; e < NEXP; e++) cnt[e] = atomicAdd(&g_counts[e], 0);
            int acc = 0;
#pragma unroll
            for (int e = 0; e < NEXP; e++) { g_offsets[e] = acc; acc += cnt[e]; }
            g_offsets[NEXP] = acc;
            int nt = 0;
#pragma unroll
            for (int e = 0; e < NEXP; e++)
                for (int m0 = 0; m0 < cnt[e]; m0 += 128)
                    g_tile[nt++] = make_int2(e, m0);
            while (nt < MAXTILE) g_tile[nt++] = make_int2(-1, 0);
            __threadfence();
        }
    }
}

// fused scatter + gather: block = (token, slot) assignment; copies row to xbuf
__global__ void k_scatgather(const float* __restrict__ x)
{
    __shared__ int s_pos;
    const int idx = blockIdx.x;          // 0..MTOT-1
    const int tok = idx >> 1;
    if (threadIdx.x == 0) {
        int e = g_tok_e[idx];
        int pos = g_offsets[e] + atomicAdd(&g_cursor[e], 1);
        g_perm[pos] = tok;
        g_wgt[pos]  = g_tok_w[idx];
        s_pos = pos;
    }
    __syncthreads();
    const int pos = s_pos;
    const float4* s = (const float4*)(x + (size_t)tok * DDIM);
    uint4* d = (uint4*)(g_xbuf + (size_t)pos * DDIM);
    int i = threadIdx.x;                 // 128 threads x 8 floats
    float4 v0 = s[2 * i], v1 = s[2 * i + 1];
    uint4 o;
    o.x = pack2(v0.x, v0.y); o.y = pack2(v0.z, v0.w);
    o.z = pack2(v1.x, v1.y); o.w = pack2(v1.z, v1.w);
    d[i] = o;
}

// ================= fp16 tensor-core grouped GEMM (proven 725.0us config) =====
// CTA tile 128(M) x 256(N), K-chunk 32, 4-stage cp.async pipeline.
// 8 warps 2x4; warp tile 64x64. SMEM halves: A [128][40], B k-major [32][264].
// GEMM1 additionally carries CONV_ROWS early grid.y rows that convert W2->fp16.
#define ASTR 40
#define BSTR 264
#define A_HALVES (128 * ASTR)
#define B_HALVES (32 * BSTR)
#define STAGE_BYTES ((A_HALVES + B_HALVES) * 2)
#define SMEM_BYTES (4 * STAGE_BYTES)
#define CONV_ROWS 4        // 4 x 16 = 64 conversion CTAs (GEMM1 only)

template<int KTOT, int NDIM, bool IS_G1>
__global__ __launch_bounds__(256)
void k_tc(const __half* __restrict__ Asrc, const __half* __restrict__ Bsrc,
          const float* __restrict__ bias, float* __restrict__ outp,
          const float4* __restrict__ cvsrc, uint4* __restrict__ cvdst)
{
    if (IS_G1 && blockIdx.y < CONV_ROWS) {
        // W2 fp32->fp16 conversion, scheduled in the first wave of GEMM1
        const int cid = blockIdx.y * gridDim.x + blockIdx.x;   // 0..63
        int i = cid * 256 + threadIdx.x;
        const int stride = CONV_ROWS * 16 * 256;
        for (; i < WN8; i += stride) conv8(cvsrc, cvdst, i);
        return;
    }
    const int2 tl = g_tile[blockIdx.y - (IS_G1 ? CONV_ROWS : 0)];
    if (tl.x < 0) return;
    const int e  = tl.x;
    const int m0 = tl.y;
    const int n0 = blockIdx.x * 256;
    const int base = g_offsets[e];
    const int cnt  = g_offsets[e + 1] - base;

    extern __shared__ __half smh[];
    const uint32_t s0 = smem_u32(smh);

    const int tid  = threadIdx.x;
    const int wid  = tid >> 5, lane = tid & 31;
    const int wm   = wid >> 2, wn = wid & 3;
    const int lr   = lane >> 2, lc = lane & 3;

    const __half* Abase = Asrc + (size_t)(base + m0) * KTOT;
    const __half* Bbase = Bsrc + (size_t)e * KTOT * NDIM + n0;

    float acc[4][8][4];
#pragma unroll
    for (int i = 0; i < 4; i++)
#pragma unroll
        for (int j = 0; j < 8; j++)
#pragma unroll
            for (int k = 0; k < 4; k++) acc[i][j][k] = 0.f;

    constexpr int NC = KTOT / 32;

    const int am  = tid >> 1;
    const int aj  = (tid & 1) * 2;
    const int bk  = tid >> 3;
    const int bj  = (tid & 7) * 4;

    auto load_chunk = [&](int c) {
        const uint32_t sa = s0 + (uint32_t)(c & 3) * STAGE_BYTES;
        const uint32_t sb = sa + A_HALVES * 2;
        const int k0 = c * 32;
#pragma unroll
        for (int j = 0; j < 2; j++)
            cp16(sa + (uint32_t)(am * ASTR + (aj + j) * 8) * 2,
                 Abase + (size_t)am * KTOT + k0 + (aj + j) * 8);
#pragma unroll
        for (int j = 0; j < 4; j++)
            cp16(sb + (uint32_t)(bk * BSTR + (bj + j) * 8) * 2,
                 Bbase + (size_t)(k0 + bk) * NDIM + (bj + j) * 8);
        cp_commit();
    };

    load_chunk(0);
    load_chunk(1);
    load_chunk(2);

    const uint32_t a_off = (uint32_t)((wm * 64 + (lane & 15)) * ASTR + (lane >> 4) * 8) * 2;
    const uint32_t b_off = (uint32_t)(((lane & 7) + 8 * ((lane >> 3) & 1)) * BSTR
                                      + wn * 64 + 8 * (lane >> 4)) * 2 + A_HALVES * 2;

#pragma unroll 1
    for (int c = 0; c < NC; c++) {
        asm volatile("cp.async.wait_group 2;" ::: "memory");
        __syncthreads();
        if (c + 3 < NC) load_chunk(c + 3);
        else cp_commit();

        const uint32_t st = s0 + (uint32_t)(c & 3) * STAGE_BYTES;
#pragma unroll
        for (int kk = 0; kk < 2; kk++) {
            uint32_t a[4][4], b[4][4];
#pragma unroll
            for (int mt = 0; mt < 4; mt++)
                ldm_x4(a[mt], st + a_off + (uint32_t)(mt * 16 * ASTR + kk * 16) * 2);
#pragma unroll
            for (int np = 0; np < 4; np++)
                ldm_x4t(b[np], st + b_off + (uint32_t)(np * 16 + kk * 16 * BSTR) * 2);
#pragma unroll
            for (int mt = 0; mt < 4; mt++)
#pragma unroll
                for (int nt = 0; nt < 8; nt++)
                    mma_f16(acc[mt][nt], a[mt], b[nt >> 1][(nt & 1) * 2],
                            b[nt >> 1][(nt & 1) * 2 + 1]);
        }
    }

    // ---- epilogue
#pragma unroll
    for (int mt = 0; mt < 4; mt++) {
        const int r0 = m0 + wm * 64 + mt * 16 + lr;
        const int r1 = r0 + 8;
        const bool v0 = r0 < cnt, v1 = r1 < cnt;
        int tok0 = 0, tok1 = 0;
        float wt0 = 0.f, wt1 = 0.f;
        if (!IS_G1) {
            tok0 = g_perm[base + r0]; wt0 = g_wgt[base + r0];
            tok1 = g_perm[base + r1]; wt1 = g_wgt[base + r1];
        }
#pragma unroll
        for (int nt = 0; nt < 8; nt++) {
            const int col = n0 + wn * 64 + nt * 8 + 2 * lc;
            const float bv0 = __ldg(bias + e * NDIM + col);
            const float bv1 = __ldg(bias + e * NDIM + col + 1);
            float c0 = acc[mt][nt][0] + bv0;
            float c1 = acc[mt][nt][1] + bv1;
            float c2 = acc[mt][nt][2] + bv0;
            float c3 = acc[mt][nt][3] + bv1;
            if (IS_G1) {
                c0 = 0.5f * c0 * (1.f + erff(c0 * 0.70710678118654752f));
                c1 = 0.5f * c1 * (1.f + erff(c1 * 0.70710678118654752f));
                c2 = 0.5f * c2 * (1.f + erff(c2 * 0.70710678118654752f));
                c3 = 0.5f * c3 * (1.f + erff(c3 * 0.70710678118654752f));
                __half* hp = (__half*)outp;
                if (v0) *(uint32_t*)&hp[(size_t)(base + r0) * NDIM + col] = pack2(c0, c1);
                if (v1) *(uint32_t*)&hp[(size_t)(base + r1) * NDIM + col] = pack2(c2, c3);
            } else {
                if (v0) {
                    atomicAdd(&outp[(size_t)tok0 * NDIM + col],     wt0 * c0);
                    atomicAdd(&outp[(size_t)tok0 * NDIM + col + 1], wt0 * c1);
                }
                if (v1) {
                    atomicAdd(&outp[(size_t)tok1 * NDIM + col],     wt1 * c2);
                    atomicAdd(&outp[(size_t)tok1 * NDIM + col + 1], wt1 * c3);
                }
            }
        }
    }
}

// ================= host side =================================================
extern "C" void kernel_launch(void* const* d_in, const int* in_sizes, int n_in,
                              void* d_out, int out_size)
{
    const float* x     = (const float*)d_in[0];
    const float* emb   = (const float*)d_in[1];
    const float* W1    = (const float*)d_in[2];
    const float* b1    = (const float*)d_in[3];
    const float* W2    = (const float*)d_in[4];
    const float* b2    = (const float*)d_in[5];
    const float* cache = (const float*)d_in[6];
    float* out = (float*)d_out;

    void *xbuf, *hbuf, *w1h, *w2h;
    cudaGetSymbolAddress(&xbuf, g_xbuf);
    cudaGetSymbolAddress(&hbuf, g_hbuf);
    cudaGetSymbolAddress(&w1h, g_w1h);
    cudaGetSymbolAddress(&w2h, g_w2h);

    cudaFuncSetAttribute(k_tc<DDIM, HDIM, true>,
                         cudaFuncAttributeMaxDynamicSharedMemorySize, SMEM_BYTES);
    cudaFuncSetAttribute(k_tc<HDIM, DDIM, false>,
                         cudaFuncAttributeMaxDynamicSharedMemorySize, SMEM_BYTES);

    // zero + expert norms (tiny)
    k_prep<<<NZB + NEXP, 256>>>(out, emb);
    // routing + W1 conversion + inline scheduler (last routing block)
    k_route<<<NRB + NCV1, 256>>>(x, emb, cache, (const float4*)W1, (uint4*)w1h);
    // fused scatter + gather-convert
    k_scatgather<<<MTOT, 128>>>(x);

    // GEMM1: h = gelu(xbuf @ W1 + b1); first 64 CTAs convert W2 (for GEMM2)
    {
        dim3 grid(HDIM / 256, MAXTILE + CONV_ROWS);
        k_tc<DDIM, HDIM, true><<<grid, 256, SMEM_BYTES>>>(
            (const __half*)xbuf, (const __half*)w1h, b1, (float*)hbuf,
            (const float4*)W2, (uint4*)w2h);
    }
    // GEMM2: out[tok] += w * (hbuf @ W2 + b2)
    {
        dim3 grid(DDIM / 256, MAXTILE);
        k_tc<HDIM, DDIM, false><<<grid, 256, SMEM_BYTES>>>(
            (const __half*)hbuf, (const __half*)w2h, b2, out,
            nullptr, nullptr);
    }
}